// round 7
// baseline (speedup 1.0000x reference)
#include <cuda_runtime.h>
#include <cuda_fp16.h>
#include <cstdint>

// ---------------------------------------------------------------------------
// Problem constants
// ---------------------------------------------------------------------------
#define KDIM 256
#define NDIM 256
#define KC   64                     // K chunk: 64 fp16 = 128B row
#define NCHUNK (KDIM / KC)          // 4
#define NTHR 256                    // 8 warps
#define BM 128                      // CTA M tile
#define BN 128                      // CTA N tile (half of NDIM)

// SMEM layout (bytes)
#define OFF_A     0
#define A_BUF     (BM * 128)                     // 16384
#define OFF_B     (2 * A_BUF)                    // 32768
#define B_CHUNK   (BN * 128)                     // 16384
#define SMEM_TOTAL (OFF_B + NCHUNK * B_CHUNK)    // 98304 (2 CTAs/SM: 192KB)

// ---------------------------------------------------------------------------
// Prologue outputs: fp16 pre-swizzled B images + cubic table (gmem, L1-hot)
// ---------------------------------------------------------------------------
__device__ __align__(16) unsigned char g_Bf[NCHUNK][NDIM * 128];
__device__ __align__(16) float4 g_tab[256 * 6];

// ---------------------------------------------------------------------------
// helpers
// ---------------------------------------------------------------------------
__device__ __forceinline__ uint32_t smem_u32(const void* p) {
    uint32_t a;
    asm("{ .reg .u64 t; cvta.to.shared.u64 t, %1; cvt.u32.u64 %0, t; }" : "=r"(a) : "l"(p));
    return a;
}

__device__ __forceinline__ void ldsm_x4(uint32_t& r0, uint32_t& r1, uint32_t& r2,
                                        uint32_t& r3, uint32_t addr) {
    asm volatile("ldmatrix.sync.aligned.m8n8.x4.shared.b16 {%0,%1,%2,%3}, [%4];"
                 : "=r"(r0), "=r"(r1), "=r"(r2), "=r"(r3) : "r"(addr));
}

__device__ __forceinline__ void mma_fp16(float* c, const uint32_t* a,
                                         uint32_t b0, uint32_t b1) {
    asm volatile(
        "mma.sync.aligned.m16n8k16.row.col.f32.f16.f16.f32 "
        "{%0,%1,%2,%3}, {%4,%5,%6,%7}, {%8,%9}, {%0,%1,%2,%3};"
        : "+f"(c[0]), "+f"(c[1]), "+f"(c[2]), "+f"(c[3])
        : "r"(a[0]), "r"(a[1]), "r"(a[2]), "r"(a[3]), "r"(b0), "r"(b1));
}

#define CP_ASYNC16(saddr, gptr) \
    asm volatile("cp.async.cg.shared.global [%0], [%1], 16;" :: "r"(saddr), "l"(gptr))
#define CP_COMMIT() asm volatile("cp.async.commit_group;")
#define CP_WAIT0()  asm volatile("cp.async.wait_group 0;")

__device__ __forceinline__ uint32_t pack_h2(float a0, float a1) {
    __half2 h = __floats2half2_rn(a0, a1);
    return *reinterpret_cast<uint32_t*>(&h);
}

// ---------------------------------------------------------------------------
// Prologue: fp16 pre-swizzled B images + per-channel piecewise-cubic table
// ---------------------------------------------------------------------------
__global__ void kan_prologue(const float* __restrict__ ic, const float* __restrict__ oc) {
    if (blockIdx.x < 32) {
        int gid = blockIdx.x * 256 + threadIdx.x;   // 0..8191
        int n   = gid >> 5;                          // B row 0..255
        int g   = gid & 31;                          // k-granule (8 fp32)
        int chunk = g >> 3;
        int colg  = g & 7;
        const float4* src = (const float4*)(oc + n * KDIM + g * 8);
        float4 v0 = src[0], v1 = src[1];
        float a[8] = {v0.x, v0.y, v0.z, v0.w, v1.x, v1.y, v1.z, v1.w};
        uint32_t h[4];
#pragma unroll
        for (int e = 0; e < 4; e++) h[e] = pack_h2(a[2 * e], a[2 * e + 1]);
        int off = n * 128 + ((colg ^ (n & 7)) << 4);
        *(uint4*)(g_Bf[chunk] + off) = make_uint4(h[0], h[1], h[2], h[3]);
    } else {
        // tab[k][j] = c0*S_j + c1*S_{j-1} (uniform cubic B-spline segments /6)
        int k = threadIdx.x;
        float c0 = ic[k * 5 + 0];
        float c1 = ic[k * 5 + 1];
        const float P[4][4] = {
            {0.f, 0.f, 0.f,  1.f},
            {1.f, 3.f, 3.f, -3.f},
            {4.f, 0.f, -6.f, 3.f},
            {1.f, -3.f, 3.f, -1.f}
        };
        const float s6 = 1.0f / 6.0f;
#pragma unroll
        for (int j = 0; j < 6; j++) {
            float q[4] = {0.f, 0.f, 0.f, 0.f};
            if (j <= 3)
                for (int d = 0; d < 4; d++) q[d] += c0 * P[j][d];
            if (j >= 1 && j <= 4)
                for (int d = 0; d < 4; d++) q[d] += c1 * P[j - 1][d];
            g_tab[k * 6 + j] = make_float4(q[0] * s6, q[1] * s6, q[2] * s6, q[3] * s6);
        }
    }
}

// ---------------------------------------------------------------------------
__device__ __forceinline__ float kan_eval(float xv, int k) {
    float e2 = __expf(2.0f * xv);
    float t  = 1.0f - __fdividef(2.0f, e2 + 1.0f);   // tanh
    float v  = fmaf(t, 3.5f, 3.5f);                   // (t+1)/h
    int j = (int)v;
    j = j > 5 ? 5 : j;                                // slot 5 == zeros
    float u = v - (float)j;
    float4 p = __ldg(&g_tab[k * 6 + j]);              // L1-resident table
    return fmaf(fmaf(fmaf(p.w, u, p.z), u, p.y), u, p.x);
}

// act 16 elems (one row, one k-quarter) -> swizzled fp16 smem row
__device__ __forceinline__ void act_store16(const float4* xv, int kb,
                                            char* ad, int swg0, int swg1) {
    float av[16] = {xv[0].x, xv[0].y, xv[0].z, xv[0].w, xv[1].x, xv[1].y, xv[1].z, xv[1].w,
                    xv[2].x, xv[2].y, xv[2].z, xv[2].w, xv[3].x, xv[3].y, xv[3].z, xv[3].w};
    float r[16];
#pragma unroll
    for (int e = 0; e < 16; e++) r[e] = kan_eval(av[e], kb + e);
    *(uint4*)(ad + swg0) = make_uint4(pack_h2(r[0], r[1]),   pack_h2(r[2], r[3]),
                                      pack_h2(r[4], r[5]),   pack_h2(r[6], r[7]));
    *(uint4*)(ad + swg1) = make_uint4(pack_h2(r[8], r[9]),   pack_h2(r[10], r[11]),
                                      pack_h2(r[12], r[13]), pack_h2(r[14], r[15]));
}

// ---------------------------------------------------------------------------
// Main: CTA computes C[128 x 128] = act(X[128 x 256]) @ W[n-half]^T.
// B resident in smem (loaded once); A double-buffered; 1 barrier per chunk.
// ---------------------------------------------------------------------------
__global__ void __launch_bounds__(NTHR, 2)
kan_main(const float* __restrict__ x, float* __restrict__ out) {
    extern __shared__ __align__(1024) char smem[];
    const int tid = threadIdx.x;
    const int wid = tid >> 5;
    const int lid = tid & 31;
    const int m0  = (blockIdx.x >> 1) * BM;
    const int n0  = (blockIdx.x & 1) * BN;

    const uint32_t sbase = smem_u32(smem);

    // warp tile: 32 (M) x 64 (N); 8 warps = 4 x 2
    const int wm = (wid >> 1) * 32;
    const int wn = (wid & 1) * 64;

    // ---- load all B chunks for this N-half (once) ----
#pragma unroll
    for (int ch = 0; ch < NCHUNK; ch++) {
        const char* src = (const char*)g_Bf[ch] + n0 * 128;
        uint32_t dst = sbase + OFF_B + ch * B_CHUNK;
#pragma unroll
        for (int i = 0; i < 4; i++) {
            int idx = tid + i * NTHR;                // 0..1023 granules
            CP_ASYNC16(dst + idx * 16, src + idx * 16);
        }
    }
    CP_COMMIT();

    // ---- per-thread activation geometry: 2 rows x 16 k per chunk ----
    const int row0 = tid >> 2;           // 0..63
    const int row1 = row0 + 64;          // 64..127  (row1 & 7 == row0 & 7)
    const int aq   = tid & 3;            // k-quarter
    const int swg0 = ((aq * 2)     ^ (row0 & 7)) << 4;
    const int swg1 = ((aq * 2 + 1) ^ (row0 & 7)) << 4;
    const float4* xb0 = (const float4*)(x + (size_t)(m0 + row0) * KDIM + aq * 16);
    const float4* xb1 = (const float4*)(x + (size_t)(m0 + row1) * KDIM + aq * 16);

    // ---- chunk 0: load x, activate into A buf 0 (overlaps B cp.async) ----
    float4 xv0[4], xv1[4];
#pragma unroll
    for (int i = 0; i < 4; i++) { xv0[i] = xb0[i]; xv1[i] = xb1[i]; }
    {
        char* a0 = smem + OFF_A;
        act_store16(xv0, aq * 16, a0 + row0 * 128, swg0, swg1);
        act_store16(xv1, aq * 16, a0 + row1 * 128, swg0, swg1);
    }

    float acc[2][8][4];
#pragma unroll
    for (int mt = 0; mt < 2; mt++)
#pragma unroll
        for (int nt = 0; nt < 8; nt++)
#pragma unroll
            for (int e = 0; e < 4; e++) acc[mt][nt][e] = 0.0f;

    const int lr   = lid & 15;
    const int lhal = lid >> 4;

    CP_WAIT0();                          // B resident

#pragma unroll
    for (int c = 0; c < NCHUNK; c++) {
        const int s = c & 1;
        __syncthreads();                 // A(c)+B visible; A(alt) readers done

        // ---- prefetch x(c+1) ----
        if (c < NCHUNK - 1) {
#pragma unroll
            for (int i = 0; i < 4; i++) {
                xv0[i] = xb0[(c + 1) * (KC / 16) * 4 / 4 + (c + 1) * 0 + i + (c + 1) * 4];
            }
        }
        // (indexing hack above is wrong-prone; use explicit pointers instead)
        if (c < NCHUNK - 1) {
            const float4* p0 = xb0 + (c + 1) * (KC / 4);
            const float4* p1 = xb1 + (c + 1) * (KC / 4);
#pragma unroll
            for (int i = 0; i < 4; i++) { xv0[i] = p0[i]; xv1[i] = p1[i]; }
        }

        // ---- MMA(c): 4 ksteps ----
        const uint32_t aBase = sbase + OFF_A + s * A_BUF;
        const uint32_t bBase = sbase + OFF_B + c * B_CHUNK;
#pragma unroll
        for (int ks = 0; ks < 4; ks++) {
            const int g = ks * 2 + lhal;
            uint32_t a[2][4];
#pragma unroll
            for (int mt = 0; mt < 2; mt++) {
                int r = wm + mt * 16 + lr;
                uint32_t off = (uint32_t)(r * 128 + ((g ^ (r & 7)) << 4));
                ldsm_x4(a[mt][0], a[mt][1], a[mt][2], a[mt][3], aBase + off);
            }
#pragma unroll
            for (int np = 0; np < 4; np++) {
                int r = wn + np * 16 + lr;
                uint32_t off = (uint32_t)(r * 128 + ((g ^ (r & 7)) << 4));
                uint32_t b[4];
                ldsm_x4(b[0], b[1], b[2], b[3], bBase + off);
#pragma unroll
                for (int mt = 0; mt < 2; mt++) {
                    mma_fp16(acc[mt][2 * np + 0], a[mt], b[0], b[2]);
                    mma_fp16(acc[mt][2 * np + 1], a[mt], b[1], b[3]);
                }
            }
        }

        // ---- act(c+1) -> other A buffer ----
        if (c < NCHUNK - 1) {
            char* ad = smem + OFF_A + (s ^ 1) * A_BUF;
            int kb = (c + 1) * KC + aq * 16;
            act_store16(xv0, kb, ad + row0 * 128, swg0, swg1);
            act_store16(xv1, kb, ad + row1 * 128, swg0, swg1);
        }
    }

    // ---- epilogue: direct fp32 stores ----
    {
        const int rq = lid >> 2;
        const int cq = (lid & 3) * 2;
#pragma unroll
        for (int mt = 0; mt < 2; mt++) {
            int row = m0 + wm + mt * 16 + rq;
#pragma unroll
            for (int nt = 0; nt < 8; nt++) {
                int col = n0 + wn + nt * 8 + cq;
                float2 v0 = make_float2(acc[mt][nt][0], acc[mt][nt][1]);
                float2 v1 = make_float2(acc[mt][nt][2], acc[mt][nt][3]);
                *(float2*)(out + (size_t)row * NDIM + col)       = v0;
                *(float2*)(out + (size_t)(row + 8) * NDIM + col) = v1;
            }
        }
    }
}

// ---------------------------------------------------------------------------
extern "C" void kernel_launch(void* const* d_in, const int* in_sizes, int n_in,
                              void* d_out, int out_size) {
    const float* x  = (const float*)d_in[0];   // [B,S,256] fp32
    const float* ic = (const float*)d_in[1];   // [256,5]   fp32
    const float* oc = (const float*)d_in[2];   // [256,256] fp32
    float* out = (float*)d_out;

    const int M = in_sizes[0] / KDIM;          // 65536

    cudaFuncSetAttribute(kan_main, cudaFuncAttributeMaxDynamicSharedMemorySize, SMEM_TOTAL);

    kan_prologue<<<33, 256>>>(ic, oc);
    kan_main<<<(M / BM) * 2, NTHR, SMEM_TOTAL>>>(x, out);
}

// round 8
// speedup vs baseline: 1.2387x; 1.2387x over previous
#include <cuda_runtime.h>
#include <cuda_fp16.h>
#include <cstdint>

// ---------------------------------------------------------------------------
// Problem constants
// ---------------------------------------------------------------------------
#define KDIM 256
#define NDIM 256
#define KC   64                    // K chunk: 64 fp16 = 128B row
#define NCHUNK (KDIM / KC)
#define NTHR 512                   // 16 warps

// SMEM layout (bytes)
#define OFF_TAB   0
#define TAB_BYTES (256 * 6 * 16)                 // 24576
#define OFF_TT    24576                          // tanh table: 64 x float4
#define OFF_A     25600
#define A_BUF     (128 * 128)                    // 16384
#define OFF_B     (OFF_A + 2 * A_BUF)            // 58368
#define B_BUF     (256 * 128)                    // 32768
#define SMEM_TOTAL (OFF_B + 2 * B_BUF)           // 123904

// tanh-table geometry: v(x)=3.5*(tanh(x)+1) on [XLO, XHI], 64 Hermite segments
#define XLO  (-5.5f)
#define XHI  (0.6f)
#define TSEG 64

// ---------------------------------------------------------------------------
// Prologue outputs
// ---------------------------------------------------------------------------
__device__ __align__(16) unsigned char g_Bf[NCHUNK][NDIM * 128];
__device__ __align__(16) float4 g_tab[256 * 6];
__device__ __align__(16) float4 g_ttab[TSEG];

// ---------------------------------------------------------------------------
// helpers
// ---------------------------------------------------------------------------
__device__ __forceinline__ uint32_t smem_u32(const void* p) {
    uint32_t a;
    asm("{ .reg .u64 t; cvta.to.shared.u64 t, %1; cvt.u32.u64 %0, t; }" : "=r"(a) : "l"(p));
    return a;
}

__device__ __forceinline__ void ldsm_x4(uint32_t& r0, uint32_t& r1, uint32_t& r2,
                                        uint32_t& r3, uint32_t addr) {
    asm volatile("ldmatrix.sync.aligned.m8n8.x4.shared.b16 {%0,%1,%2,%3}, [%4];"
                 : "=r"(r0), "=r"(r1), "=r"(r2), "=r"(r3) : "r"(addr));
}

__device__ __forceinline__ void mma_fp16(float* c, const uint32_t* a,
                                         uint32_t b0, uint32_t b1) {
    asm volatile(
        "mma.sync.aligned.m16n8k16.row.col.f32.f16.f16.f32 "
        "{%0,%1,%2,%3}, {%4,%5,%6,%7}, {%8,%9}, {%0,%1,%2,%3};"
        : "+f"(c[0]), "+f"(c[1]), "+f"(c[2]), "+f"(c[3])
        : "r"(a[0]), "r"(a[1]), "r"(a[2]), "r"(a[3]), "r"(b0), "r"(b1));
}

#define CP_ASYNC16(saddr, gptr) \
    asm volatile("cp.async.cg.shared.global [%0], [%1], 16;" :: "r"(saddr), "l"(gptr))
#define CP_COMMIT() asm volatile("cp.async.commit_group;")
#define CP_WAIT0()  asm volatile("cp.async.wait_group 0;")

__device__ __forceinline__ uint32_t pack_h2(float a0, float a1) {
    __half2 h = __floats2half2_rn(a0, a1);
    return *reinterpret_cast<uint32_t*>(&h);
}

// ---------------------------------------------------------------------------
// Prologue: fp16 pre-swizzled B images + channel cubic table + tanh table
// ---------------------------------------------------------------------------
__global__ void kan_prologue(const float* __restrict__ ic, const float* __restrict__ oc) {
    if (blockIdx.x < 32) {
        int gid = blockIdx.x * 256 + threadIdx.x;   // 0..8191
        int n   = gid >> 5;                          // B row 0..255
        int g   = gid & 31;                          // k-granule (8 fp32)
        int chunk = g >> 3;
        int colg  = g & 7;
        const float4* src = (const float4*)(oc + n * KDIM + g * 8);
        float4 v0 = src[0], v1 = src[1];
        float a[8] = {v0.x, v0.y, v0.z, v0.w, v1.x, v1.y, v1.z, v1.w};
        uint32_t h[4];
#pragma unroll
        for (int e = 0; e < 4; e++) h[e] = pack_h2(a[2 * e], a[2 * e + 1]);
        int off = n * 128 + ((colg ^ (n & 7)) << 4);
        *(uint4*)(g_Bf[chunk] + off) = make_uint4(h[0], h[1], h[2], h[3]);
    } else {
        int k = threadIdx.x;
        // ---- channel table: tab[k][j] = c0*S_j + c1*S_{j-1} (/6) ----
        float c0 = ic[k * 5 + 0];
        float c1 = ic[k * 5 + 1];
        const float P[4][4] = {
            {0.f, 0.f, 0.f,  1.f},
            {1.f, 3.f, 3.f, -3.f},
            {4.f, 0.f, -6.f, 3.f},
            {1.f, -3.f, 3.f, -1.f}
        };
        const float s6 = 1.0f / 6.0f;
#pragma unroll
        for (int j = 0; j < 6; j++) {
            float q[4] = {0.f, 0.f, 0.f, 0.f};
            if (j <= 3)
                for (int d = 0; d < 4; d++) q[d] += c0 * P[j][d];
            if (j >= 1 && j <= 4)
                for (int d = 0; d < 4; d++) q[d] += c1 * P[j - 1][d];
            g_tab[k * 6 + j] = make_float4(q[0] * s6, q[1] * s6, q[2] * s6, q[3] * s6);
        }
        // ---- tanh table: Hermite cubic per segment, built in double ----
        if (k < TSEG) {
            double h = (double)(XHI - XLO) / TSEG;
            double x0 = (double)XLO + k * h, x1 = x0 + h;
            double t0 = tanh(x0), t1 = tanh(x1);
            double f0 = 3.5 * (t0 + 1.0), f1 = 3.5 * (t1 + 1.0);
            double g0 = 3.5 * (1.0 - t0 * t0) * h;
            double g1 = 3.5 * (1.0 - t1 * t1) * h;
            double A = f0, B = g0;
            double C = 3.0 * (f1 - f0) - 2.0 * g0 - g1;
            double D = 2.0 * (f0 - f1) + g0 + g1;
            g_ttab[k] = make_float4((float)A, (float)B, (float)C, (float)D);
        }
    }
}

// ---------------------------------------------------------------------------
// Hot-path activation: MUFU-free, CVT-free.
//   v = pwcubic_tanh(x);  j = floor(v) (RZ magic);  inner = chan cubic(u)
// ---------------------------------------------------------------------------
#define MAGIC 12582912.0f            /* 1.5 * 2^23 */
#define MAGIC_I 0x4B400000

__device__ __forceinline__ float kan_eval(float xv, const float4* __restrict__ tab,
                                          const float4* __restrict__ ttab, int k) {
    // stage 1: v(x) via 64-seg Hermite table
    float xc = fminf(fmaxf(xv, XLO), XHI);
    float w  = (xc - XLO) * ((float)TSEG / (XHI - XLO));
    float wf = __fadd_rz(w, MAGIC);
    int   seg = __float_as_int(wf) - MAGIC_I;
    float segf = wf - MAGIC;
    seg  = seg > TSEG - 1 ? TSEG - 1 : seg;
    segf = fminf(segf, (float)(TSEG - 1));
    float uu = w - segf;
    float4 q = ttab[seg];
    float v = fmaf(fmaf(fmaf(q.w, uu, q.z), uu, q.y), uu, q.x);
    v = fmaxf(v, 0.0f);
    // stage 2: channel spline segment
    float vf = __fadd_rz(v, MAGIC);
    int   j  = __float_as_int(vf) - MAGIC_I;
    float jf = vf - MAGIC;
    j  = j > 5 ? 5 : j;
    jf = fminf(jf, 5.0f);
    float u = v - jf;
    float4 p = tab[k * 6 + j];
    return fmaf(fmaf(fmaf(p.w, u, p.z), u, p.y), u, p.x);
}

// ---------------------------------------------------------------------------
// Main: CTA computes C[128 x 256] = act(X[128 x 256]) @ W^T, fp16 HMMA,
// activation for chunk c+1 fused into the MMA phase of chunk c.  (R6 structure)
// ---------------------------------------------------------------------------
__global__ void __launch_bounds__(NTHR, 1)
kan_main(const float* __restrict__ x, float* __restrict__ out) {
    extern __shared__ __align__(1024) char smem[];
    const int tid = threadIdx.x;
    const int wid = tid >> 5;
    const int lid = tid & 31;
    const int m0  = blockIdx.x * 128;

    const uint32_t sbase = smem_u32(smem);

    // warp tile: 32 (M) x 64 (N)
    const int wm = (wid >> 2) * 32;
    const int wn = (wid & 3) * 64;

    // ---- stage tables ----
    {
        float4* stab = (float4*)(smem + OFF_TAB);
#pragma unroll
        for (int i = 0; i < 3; i++) stab[tid + i * NTHR] = g_tab[tid + i * NTHR];
        if (tid < TSEG) ((float4*)(smem + OFF_TT))[tid] = g_ttab[tid];
    }
    // ---- issue B chunk 0 ----
    {
        uint32_t dh = sbase + OFF_B;
#pragma unroll
        for (int i = 0; i < 4; i++) {
            int idx = tid + i * NTHR;                // 0..2047
            CP_ASYNC16(dh + idx * 16, (const char*)g_Bf[0] + idx * 16);
        }
        CP_COMMIT();
    }

    // ---- x chunk 0 ----
    const int arow = tid >> 2;          // 0..127
    const int aq   = tid & 3;           // k-quarter (16 elems)
    const float4* xbase = (const float4*)(x + (size_t)(m0 + arow) * KDIM + aq * 16);
    float4 xv0 = xbase[0], xv1 = xbase[1], xv2 = xbase[2], xv3 = xbase[3];

    __syncthreads();                    // tables visible
    const float4* tab  = (const float4*)(smem + OFF_TAB);
    const float4* ttab = (const float4*)(smem + OFF_TT);

    // activation writer constants
    const int g0 = aq * 2;
    const int g1 = aq * 2 + 1;
    const int swg0 = (g0 ^ (arow & 7)) << 4;
    const int swg1 = (g1 ^ (arow & 7)) << 4;

    // ---- act(0) -> A buf 0 ----
    {
        float av[16] = {xv0.x, xv0.y, xv0.z, xv0.w, xv1.x, xv1.y, xv1.z, xv1.w,
                        xv2.x, xv2.y, xv2.z, xv2.w, xv3.x, xv3.y, xv3.z, xv3.w};
        int kb = aq * 16;
        float r[16];
#pragma unroll
        for (int e = 0; e < 16; e++) r[e] = kan_eval(av[e], tab, ttab, kb + e);
        char* ad = smem + OFF_A + arow * 128;
        *(uint4*)(ad + swg0) = make_uint4(pack_h2(r[0], r[1]),  pack_h2(r[2], r[3]),
                                          pack_h2(r[4], r[5]),  pack_h2(r[6], r[7]));
        *(uint4*)(ad + swg1) = make_uint4(pack_h2(r[8], r[9]),  pack_h2(r[10], r[11]),
                                          pack_h2(r[12], r[13]), pack_h2(r[14], r[15]));
    }

    float acc[2][8][4];
#pragma unroll
    for (int mt = 0; mt < 2; mt++)
#pragma unroll
        for (int nt = 0; nt < 8; nt++)
#pragma unroll
            for (int e = 0; e < 4; e++) acc[mt][nt][e] = 0.0f;

    const int lr   = lid & 15;          // ldmatrix row within 16
    const int lhal = lid >> 4;          // k-granule half

#pragma unroll
    for (int c = 0; c < NCHUNK; c++) {
        const int s = c & 1;

        CP_WAIT0();                     // B(c) landed (only group in flight)
        __syncthreads();                // A(c)+B(c) visible; MMA(c-1) reads done

        // ---- prefetch chunk c+1: B via cp.async, x via LDG ----
        if (c < NCHUNK - 1) {
            uint32_t dh = sbase + OFF_B + (s ^ 1) * B_BUF;
#pragma unroll
            for (int i = 0; i < 4; i++) {
                int idx = tid + i * NTHR;
                CP_ASYNC16(dh + idx * 16, (const char*)g_Bf[c + 1] + idx * 16);
            }
            CP_COMMIT();
            const float4* xp = xbase + (c + 1) * (KC / 4);
            xv0 = xp[0]; xv1 = xp[1]; xv2 = xp[2]; xv3 = xp[3];
        }

        // ---- MMA(c): 4 ksteps, single fp16 pass ----
        const uint32_t aBase = sbase + OFF_A + s * A_BUF;
        const uint32_t bBase = sbase + OFF_B + s * B_BUF;
#pragma unroll
        for (int ks = 0; ks < 4; ks++) {
            const int g = ks * 2 + lhal;
            uint32_t a[2][4];
#pragma unroll
            for (int mt = 0; mt < 2; mt++) {
                int r = wm + mt * 16 + lr;
                uint32_t off = (uint32_t)(r * 128 + ((g ^ (r & 7)) << 4));
                ldsm_x4(a[mt][0], a[mt][1], a[mt][2], a[mt][3], aBase + off);
            }
#pragma unroll
            for (int np = 0; np < 4; np++) {
                int r = wn + np * 16 + lr;
                uint32_t off = (uint32_t)(r * 128 + ((g ^ (r & 7)) << 4));
                uint32_t b[4];
                ldsm_x4(b[0], b[1], b[2], b[3], bBase + off);
#pragma unroll
                for (int mt = 0; mt < 2; mt++) {
                    mma_fp16(acc[mt][2 * np + 0], a[mt], b[0], b[2]);
                    mma_fp16(acc[mt][2 * np + 1], a[mt], b[1], b[3]);
                }
            }
        }

        // ---- act(c+1) -> other A buffer (overlaps tensor-pipe drain) ----
        if (c < NCHUNK - 1) {
            float av[16] = {xv0.x, xv0.y, xv0.z, xv0.w, xv1.x, xv1.y, xv1.z, xv1.w,
                            xv2.x, xv2.y, xv2.z, xv2.w, xv3.x, xv3.y, xv3.z, xv3.w};
            int kb = (c + 1) * KC + aq * 16;
            float r[16];
#pragma unroll
            for (int e = 0; e < 16; e++) r[e] = kan_eval(av[e], tab, ttab, kb + e);
            char* ad = smem + OFF_A + (s ^ 1) * A_BUF + arow * 128;
            *(uint4*)(ad + swg0) = make_uint4(pack_h2(r[0], r[1]),  pack_h2(r[2], r[3]),
                                              pack_h2(r[4], r[5]),  pack_h2(r[6], r[7]));
            *(uint4*)(ad + swg1) = make_uint4(pack_h2(r[8], r[9]),  pack_h2(r[10], r[11]),
                                              pack_h2(r[12], r[13]), pack_h2(r[14], r[15]));
        }
    }

    // ---- epilogue: direct fp32 stores from accumulators ----
    {
        const int rq = lid >> 2;            // 0..7
        const int cq = (lid & 3) * 2;       // 0,2,4,6
#pragma unroll
        for (int mt = 0; mt < 2; mt++) {
            int row = m0 + wm + mt * 16 + rq;
#pragma unroll
            for (int nt = 0; nt < 8; nt++) {
                int col = wn + nt * 8 + cq;
                float2 v0 = make_float2(acc[mt][nt][0], acc[mt][nt][1]);
                float2 v1 = make_float2(acc[mt][nt][2], acc[mt][nt][3]);
                *(float2*)(out + (size_t)row * NDIM + col)       = v0;
                *(float2*)(out + (size_t)(row + 8) * NDIM + col) = v1;
            }
        }
    }
}

// ---------------------------------------------------------------------------
extern "C" void kernel_launch(void* const* d_in, const int* in_sizes, int n_in,
                              void* d_out, int out_size) {
    const float* x  = (const float*)d_in[0];   // [B,S,256] fp32
    const float* ic = (const float*)d_in[1];   // [256,5]   fp32
    const float* oc = (const float*)d_in[2];   // [256,256] fp32
    float* out = (float*)d_out;

    const int M = in_sizes[0] / KDIM;          // 65536

    cudaFuncSetAttribute(kan_main, cudaFuncAttributeMaxDynamicSharedMemorySize, SMEM_TOTAL);

    kan_prologue<<<33, 256>>>(ic, oc);
    kan_main<<<M / 128, NTHR, SMEM_TOTAL>>>(x, out);
}

// round 9
// speedup vs baseline: 1.7046x; 1.3760x over previous
#include <cuda_runtime.h>
#include <cuda_fp16.h>
#include <cstdint>

// ---------------------------------------------------------------------------
// Problem constants
// ---------------------------------------------------------------------------
#define KDIM 256
#define NDIM 256
#define KC   64                    // K chunk: 64 fp16 = 128B row
#define NCHUNK (KDIM / KC)
#define NTHR 256                   // 8 warps
#define BM 64                      // CTA M tile (M-split for 2 CTAs/SM)

// SMEM layout (bytes)
#define OFF_TAB   0
#define TAB_BYTES (256 * 6 * 16)                 // 24576
#define OFF_A     24576
#define A_BUF     (BM * 128)                     // 8192
#define OFF_B     (OFF_A + 2 * A_BUF)            // 40960
#define B_BUF     (256 * 128)                    // 32768
#define SMEM_TOTAL (OFF_B + 2 * B_BUF)           // 106496 (x2 CTAs = 208KB/SM)

// ---------------------------------------------------------------------------
// Prologue outputs: fp16 pre-swizzled B images + channel cubic table
// ---------------------------------------------------------------------------
__device__ __align__(16) unsigned char g_Bf[NCHUNK][NDIM * 128];
__device__ __align__(16) float4 g_tab[256 * 6];

// ---------------------------------------------------------------------------
// helpers
// ---------------------------------------------------------------------------
__device__ __forceinline__ uint32_t smem_u32(const void* p) {
    uint32_t a;
    asm("{ .reg .u64 t; cvta.to.shared.u64 t, %1; cvt.u32.u64 %0, t; }" : "=r"(a) : "l"(p));
    return a;
}

__device__ __forceinline__ void ldsm_x4(uint32_t& r0, uint32_t& r1, uint32_t& r2,
                                        uint32_t& r3, uint32_t addr) {
    asm volatile("ldmatrix.sync.aligned.m8n8.x4.shared.b16 {%0,%1,%2,%3}, [%4];"
                 : "=r"(r0), "=r"(r1), "=r"(r2), "=r"(r3) : "r"(addr));
}

__device__ __forceinline__ void mma_fp16(float* c, const uint32_t* a,
                                         uint32_t b0, uint32_t b1) {
    asm volatile(
        "mma.sync.aligned.m16n8k16.row.col.f32.f16.f16.f32 "
        "{%0,%1,%2,%3}, {%4,%5,%6,%7}, {%8,%9}, {%0,%1,%2,%3};"
        : "+f"(c[0]), "+f"(c[1]), "+f"(c[2]), "+f"(c[3])
        : "r"(a[0]), "r"(a[1]), "r"(a[2]), "r"(a[3]), "r"(b0), "r"(b1));
}

#define CP_ASYNC16(saddr, gptr) \
    asm volatile("cp.async.cg.shared.global [%0], [%1], 16;" :: "r"(saddr), "l"(gptr))
#define CP_COMMIT() asm volatile("cp.async.commit_group;")
#define CP_WAIT0()  asm volatile("cp.async.wait_group 0;")

__device__ __forceinline__ uint32_t pack_h2(float a0, float a1) {
    __half2 h = __floats2half2_rn(a0, a1);
    return *reinterpret_cast<uint32_t*>(&h);
}

// ---------------------------------------------------------------------------
// Prologue: fp16 pre-swizzled B images + per-channel piecewise-cubic table
// ---------------------------------------------------------------------------
__global__ void kan_prologue(const float* __restrict__ ic, const float* __restrict__ oc) {
    if (blockIdx.x < 32) {
        int gid = blockIdx.x * 256 + threadIdx.x;   // 0..8191
        int n   = gid >> 5;                          // B row 0..255
        int g   = gid & 31;                          // k-granule (8 fp32)
        int chunk = g >> 3;
        int colg  = g & 7;
        const float4* src = (const float4*)(oc + n * KDIM + g * 8);
        float4 v0 = src[0], v1 = src[1];
        float a[8] = {v0.x, v0.y, v0.z, v0.w, v1.x, v1.y, v1.z, v1.w};
        uint32_t h[4];
#pragma unroll
        for (int e = 0; e < 4; e++) h[e] = pack_h2(a[2 * e], a[2 * e + 1]);
        int off = n * 128 + ((colg ^ (n & 7)) << 4);
        *(uint4*)(g_Bf[chunk] + off) = make_uint4(h[0], h[1], h[2], h[3]);
    } else {
        // tab[k][j] = c0*S_j + c1*S_{j-1} (uniform cubic B-spline segments /6)
        int k = threadIdx.x;
        float c0 = ic[k * 5 + 0];
        float c1 = ic[k * 5 + 1];
        const float P[4][4] = {
            {0.f, 0.f, 0.f,  1.f},
            {1.f, 3.f, 3.f, -3.f},
            {4.f, 0.f, -6.f, 3.f},
            {1.f, -3.f, 3.f, -1.f}
        };
        const float s6 = 1.0f / 6.0f;
#pragma unroll
        for (int j = 0; j < 6; j++) {
            float q[4] = {0.f, 0.f, 0.f, 0.f};
            if (j <= 3)
                for (int d = 0; d < 4; d++) q[d] += c0 * P[j][d];
            if (j >= 1 && j <= 4)
                for (int d = 0; d < 4; d++) q[d] += c1 * P[j - 1][d];
            g_tab[k * 6 + j] = make_float4(q[0] * s6, q[1] * s6, q[2] * s6, q[3] * s6);
        }
    }
}

// ---------------------------------------------------------------------------
// Hot-path activation (R6 variant: MUFU tanh + one smem table LDS)
// ---------------------------------------------------------------------------
__device__ __forceinline__ float kan_eval(float xv, const float4* __restrict__ tab, int k) {
    float e2 = __expf(2.0f * xv);
    float t  = 1.0f - __fdividef(2.0f, e2 + 1.0f);   // tanh
    float v  = fmaf(t, 3.5f, 3.5f);                   // (t+1)/h
    int j = (int)v;
    j = j > 5 ? 5 : j;                                // slot 5 == zeros
    float u = v - (float)j;
    float4 p = tab[k * 6 + j];
    return fmaf(fmaf(fmaf(p.w, u, p.z), u, p.y), u, p.x);
}

// ---------------------------------------------------------------------------
// Main: CTA computes C[64 x 256] = act(X[64 x 256]) @ W^T, fp16 HMMA.
// R6 pipeline; M-split so 2 CTAs co-reside per SM.
// ---------------------------------------------------------------------------
__global__ void __launch_bounds__(NTHR, 2)
kan_main(const float* __restrict__ x, float* __restrict__ out) {
    extern __shared__ __align__(1024) char smem[];
    const int tid = threadIdx.x;
    const int wid = tid >> 5;
    const int lid = tid & 31;
    const int m0  = blockIdx.x * BM;

    const uint32_t sbase = smem_u32(smem);

    // warp tile: 32 (M) x 64 (N); 8 warps = 2 (M) x 4 (N)
    const int wm = (wid >> 2) * 32;
    const int wn = (wid & 3) * 64;

    // ---- stage table ----
    {
        float4* stab = (float4*)(smem + OFF_TAB);
#pragma unroll
        for (int i = 0; i < 6; i++) stab[tid + i * NTHR] = g_tab[tid + i * NTHR];
    }
    // ---- issue B chunk 0 ----
    {
        uint32_t dh = sbase + OFF_B;
#pragma unroll
        for (int i = 0; i < 8; i++) {
            int idx = tid + i * NTHR;                // 0..2047 granules
            CP_ASYNC16(dh + idx * 16, (const char*)g_Bf[0] + idx * 16);
        }
        CP_COMMIT();
    }

    // ---- x chunk 0 ----
    const int arow = tid >> 2;          // 0..63
    const int aq   = tid & 3;           // k-quarter (16 elems)
    const float4* xbase = (const float4*)(x + (size_t)(m0 + arow) * KDIM + aq * 16);
    float4 xv0 = xbase[0], xv1 = xbase[1], xv2 = xbase[2], xv3 = xbase[3];

    __syncthreads();                    // table visible
    const float4* tab = (const float4*)(smem + OFF_TAB);

    // activation writer constants
    const int g0 = aq * 2;
    const int g1 = aq * 2 + 1;
    const int swg0 = (g0 ^ (arow & 7)) << 4;
    const int swg1 = (g1 ^ (arow & 7)) << 4;

    // ---- act(0) -> A buf 0 ----
    {
        float av[16] = {xv0.x, xv0.y, xv0.z, xv0.w, xv1.x, xv1.y, xv1.z, xv1.w,
                        xv2.x, xv2.y, xv2.z, xv2.w, xv3.x, xv3.y, xv3.z, xv3.w};
        int kb = aq * 16;
        float r[16];
#pragma unroll
        for (int e = 0; e < 16; e++) r[e] = kan_eval(av[e], tab, kb + e);
        char* ad = smem + OFF_A + arow * 128;
        *(uint4*)(ad + swg0) = make_uint4(pack_h2(r[0], r[1]),  pack_h2(r[2], r[3]),
                                          pack_h2(r[4], r[5]),  pack_h2(r[6], r[7]));
        *(uint4*)(ad + swg1) = make_uint4(pack_h2(r[8], r[9]),  pack_h2(r[10], r[11]),
                                          pack_h2(r[12], r[13]), pack_h2(r[14], r[15]));
    }

    float acc[2][8][4];
#pragma unroll
    for (int mt = 0; mt < 2; mt++)
#pragma unroll
        for (int nt = 0; nt < 8; nt++)
#pragma unroll
            for (int e = 0; e < 4; e++) acc[mt][nt][e] = 0.0f;

    const int lr   = lid & 15;          // ldmatrix row within 16
    const int lhal = lid >> 4;          // k-granule half

#pragma unroll
    for (int c = 0; c < NCHUNK; c++) {
        const int s = c & 1;

        CP_WAIT0();                     // B(c) landed (only group in flight)
        __syncthreads();                // A(c)+B(c) visible; MMA(c-1) reads done

        // ---- prefetch chunk c+1: B via cp.async, x via LDG ----
        if (c < NCHUNK - 1) {
            uint32_t dh = sbase + OFF_B + (s ^ 1) * B_BUF;
#pragma unroll
            for (int i = 0; i < 8; i++) {
                int idx = tid + i * NTHR;
                CP_ASYNC16(dh + idx * 16, (const char*)g_Bf[c + 1] + idx * 16);
            }
            CP_COMMIT();
            const float4* xp = xbase + (c + 1) * (KC / 4);
            xv0 = xp[0]; xv1 = xp[1]; xv2 = xp[2]; xv3 = xp[3];
        }

        // ---- MMA(c): 4 ksteps, single fp16 pass ----
        const uint32_t aBase = sbase + OFF_A + s * A_BUF;
        const uint32_t bBase = sbase + OFF_B + s * B_BUF;
#pragma unroll
        for (int ks = 0; ks < 4; ks++) {
            const int g = ks * 2 + lhal;
            uint32_t a[2][4];
#pragma unroll
            for (int mt = 0; mt < 2; mt++) {
                int r = wm + mt * 16 + lr;
                uint32_t off = (uint32_t)(r * 128 + ((g ^ (r & 7)) << 4));
                ldsm_x4(a[mt][0], a[mt][1], a[mt][2], a[mt][3], aBase + off);
            }
#pragma unroll
            for (int np = 0; np < 4; np++) {
                int r = wn + np * 16 + lr;
                uint32_t off = (uint32_t)(r * 128 + ((g ^ (r & 7)) << 4));
                uint32_t b[4];
                ldsm_x4(b[0], b[1], b[2], b[3], bBase + off);
#pragma unroll
                for (int mt = 0; mt < 2; mt++) {
                    mma_fp16(acc[mt][2 * np + 0], a[mt], b[0], b[2]);
                    mma_fp16(acc[mt][2 * np + 1], a[mt], b[1], b[3]);
                }
            }
        }

        // ---- act(c+1) -> other A buffer (overlaps tensor-pipe drain) ----
        if (c < NCHUNK - 1) {
            float av[16] = {xv0.x, xv0.y, xv0.z, xv0.w, xv1.x, xv1.y, xv1.z, xv1.w,
                            xv2.x, xv2.y, xv2.z, xv2.w, xv3.x, xv3.y, xv3.z, xv3.w};
            int kb = (c + 1) * KC + aq * 16;
            float r[16];
#pragma unroll
            for (int e = 0; e < 16; e++) r[e] = kan_eval(av[e], tab, kb + e);
            char* ad = smem + OFF_A + (s ^ 1) * A_BUF + arow * 128;
            *(uint4*)(ad + swg0) = make_uint4(pack_h2(r[0], r[1]),  pack_h2(r[2], r[3]),
                                              pack_h2(r[4], r[5]),  pack_h2(r[6], r[7]));
            *(uint4*)(ad + swg1) = make_uint4(pack_h2(r[8], r[9]),  pack_h2(r[10], r[11]),
                                              pack_h2(r[12], r[13]), pack_h2(r[14], r[15]));
        }
    }

    // ---- epilogue: direct fp32 stores from accumulators ----
    {
        const int rq = lid >> 2;            // 0..7
        const int cq = (lid & 3) * 2;       // 0,2,4,6
#pragma unroll
        for (int mt = 0; mt < 2; mt++) {
            int row = m0 + wm + mt * 16 + rq;
#pragma unroll
            for (int nt = 0; nt < 8; nt++) {
                int col = wn + nt * 8 + cq;
                float2 v0 = make_float2(acc[mt][nt][0], acc[mt][nt][1]);
                float2 v1 = make_float2(acc[mt][nt][2], acc[mt][nt][3]);
                *(float2*)(out + (size_t)row * NDIM + col)       = v0;
                *(float2*)(out + (size_t)(row + 8) * NDIM + col) = v1;
            }
        }
    }
}

// ---------------------------------------------------------------------------
extern "C" void kernel_launch(void* const* d_in, const int* in_sizes, int n_in,
                              void* d_out, int out_size) {
    const float* x  = (const float*)d_in[0];   // [B,S,256] fp32
    const float* ic = (const float*)d_in[1];   // [256,5]   fp32
    const float* oc = (const float*)d_in[2];   // [256,256] fp32
    float* out = (float*)d_out;

    const int M = in_sizes[0] / KDIM;          // 65536

    cudaFuncSetAttribute(kan_main, cudaFuncAttributeMaxDynamicSharedMemorySize, SMEM_TOTAL);

    kan_prologue<<<33, 256>>>(ic, oc);
    kan_main<<<M / BM, NTHR, SMEM_TOTAL>>>(x, out);
}

// round 10
// speedup vs baseline: 1.8904x; 1.1090x over previous
#include <cuda_runtime.h>
#include <cuda_fp16.h>
#include <cstdint>

// ---------------------------------------------------------------------------
// Problem constants
// ---------------------------------------------------------------------------
#define KDIM 256
#define NDIM 256
#define KC   64                    // K chunk: 64 fp16 = 128B row
#define NCHUNK (KDIM / KC)
#define NTHR 256                   // 8 warps
#define BM 64                      // CTA M tile (2 CTAs/SM)

// SMEM layout (bytes)
#define OFF_STAB  0                              // 8 x float4 = 128B
#define OFF_CTAB  128                            // padded (c0,c1) pairs, ~2.3KB
#define OFF_A     3072                           // 1024-aligned
#define A_BUF     (BM * 128)                     // 8192
#define OFF_B     (OFF_A + 2 * A_BUF)            // 19456 (1024-aligned)
#define B_BUF     (256 * 128)                    // 32768
#define SMEM_TOTAL (OFF_B + 2 * B_BUF)           // 84992 (x2 CTAs = 166KB/SM)

// ---------------------------------------------------------------------------
// Prologue outputs
// ---------------------------------------------------------------------------
__device__ __align__(16) unsigned char g_Bf[NCHUNK][NDIM * 128];
__device__ __align__(16) unsigned char g_ctab[2432];   // padded c0c1 image
__device__ __align__(16) float4 g_stab[8];             // segment cubics

// ---------------------------------------------------------------------------
// helpers
// ---------------------------------------------------------------------------
__device__ __forceinline__ uint32_t smem_u32(const void* p) {
    uint32_t a;
    asm("{ .reg .u64 t; cvta.to.shared.u64 t, %1; cvt.u32.u64 %0, t; }" : "=r"(a) : "l"(p));
    return a;
}

__device__ __forceinline__ void ldsm_x4(uint32_t& r0, uint32_t& r1, uint32_t& r2,
                                        uint32_t& r3, uint32_t addr) {
    asm volatile("ldmatrix.sync.aligned.m8n8.x4.shared.b16 {%0,%1,%2,%3}, [%4];"
                 : "=r"(r0), "=r"(r1), "=r"(r2), "=r"(r3) : "r"(addr));
}

__device__ __forceinline__ void mma_fp16(float* c, const uint32_t* a,
                                         uint32_t b0, uint32_t b1) {
    asm volatile(
        "mma.sync.aligned.m16n8k16.row.col.f32.f16.f16.f32 "
        "{%0,%1,%2,%3}, {%4,%5,%6,%7}, {%8,%9}, {%0,%1,%2,%3};"
        : "+f"(c[0]), "+f"(c[1]), "+f"(c[2]), "+f"(c[3])
        : "r"(a[0]), "r"(a[1]), "r"(a[2]), "r"(a[3]), "r"(b0), "r"(b1));
}

#define CP_ASYNC16(saddr, gptr) \
    asm volatile("cp.async.cg.shared.global [%0], [%1], 16;" :: "r"(saddr), "l"(gptr))
#define CP_COMMIT() asm volatile("cp.async.commit_group;")
#define CP_WAIT0()  asm volatile("cp.async.wait_group 0;")

__device__ __forceinline__ uint32_t pack_h2(float a0, float a1) {
    __half2 h = __floats2half2_rn(a0, a1);
    return *reinterpret_cast<uint32_t*>(&h);
}

// padded (c0,c1) offset: one 16B granule holds pairs for channels {k, k+1}, k even
__device__ __host__ __forceinline__ int ctab_off(int k) {
    return k * 8 + (k >> 4) * 16;
}

// ---------------------------------------------------------------------------
// Prologue: fp16 pre-swizzled B images + c0c1 pairs + segment-cubic table
// ---------------------------------------------------------------------------
__global__ void kan_prologue(const float* __restrict__ ic, const float* __restrict__ oc) {
    if (blockIdx.x < 32) {
        int gid = blockIdx.x * 256 + threadIdx.x;   // 0..8191
        int n   = gid >> 5;                          // B row 0..255
        int g   = gid & 31;                          // k-granule (8 fp32)
        int chunk = g >> 3;
        int colg  = g & 7;
        const float4* src = (const float4*)(oc + n * KDIM + g * 8);
        float4 v0 = src[0], v1 = src[1];
        float a[8] = {v0.x, v0.y, v0.z, v0.w, v1.x, v1.y, v1.z, v1.w};
        uint32_t h[4];
#pragma unroll
        for (int e = 0; e < 4; e++) h[e] = pack_h2(a[2 * e], a[2 * e + 1]);
        int off = n * 128 + ((colg ^ (n & 7)) << 4);
        *(uint4*)(g_Bf[chunk] + off) = make_uint4(h[0], h[1], h[2], h[3]);
    } else {
        int k = threadIdx.x;
        // (c0,c1) padded image
        float c0 = ic[k * 5 + 0];
        float c1 = ic[k * 5 + 1];
        *(float2*)(g_ctab + ctab_off(k)) = make_float2(c0, c1);
        // segment cubics: stab[m] = P[m-1]/6 for m=1..4, else 0.
        // Then on interval j: B31 = stab[j]·u, B30 = stab[j+1]·u.
        if (k < 8) {
            const float P[4][4] = {
                {0.f, 0.f, 0.f,  1.f},
                {1.f, 3.f, 3.f, -3.f},
                {4.f, 0.f, -6.f, 3.f},
                {1.f, -3.f, 3.f, -1.f}
            };
            float4 s = make_float4(0.f, 0.f, 0.f, 0.f);
            if (k >= 1 && k <= 4) {
                const float s6 = 1.0f / 6.0f;
                int m = k - 1;
                s = make_float4(P[m][0] * s6, P[m][1] * s6, P[m][2] * s6, P[m][3] * s6);
            }
            g_stab[k] = s;
        }
    }
}

// ---------------------------------------------------------------------------
// Hot-path activation v2: MUFU tanh + conflict-free j-indexed segment cubics
// ---------------------------------------------------------------------------
__device__ __forceinline__ float kan_act2(float xv, float c0, float c1,
                                          const float4* __restrict__ stab) {
    float e2 = __expf(2.0f * xv);
    float t  = 1.0f - __fdividef(2.0f, e2 + 1.0f);   // tanh
    float v  = fmaf(t, 3.5f, 3.5f);                   // (t+1)/h, in [0,7]
    int j = (int)v;
    j = j > 5 ? 5 : j;
    float u = v - (float)j;
    float4 sB = stab[j];        // B31 segment cubic
    float4 sA = stab[j + 1];    // B30 segment cubic
    float b30 = fmaf(fmaf(fmaf(sA.w, u, sA.z), u, sA.y), u, sA.x);
    float b31 = fmaf(fmaf(fmaf(sB.w, u, sB.z), u, sB.y), u, sB.x);
    return fmaf(c0, b30, c1 * b31);
}

// activate 16 elements (channels kb..kb+15) -> r[16]
__device__ __forceinline__ void act16(const float* av, int kb, const char* ctab,
                                      const float4* __restrict__ stab, float* r) {
#pragma unroll
    for (int p = 0; p < 8; p++) {
        int k0 = kb + 2 * p;
        float4 cg = *(const float4*)(ctab + ctab_off(k0));   // (c0,c1) x 2 channels
        r[2 * p]     = kan_act2(av[2 * p],     cg.x, cg.y, stab);
        r[2 * p + 1] = kan_act2(av[2 * p + 1], cg.z, cg.w, stab);
    }
}

// ---------------------------------------------------------------------------
// Main: CTA computes C[64 x 256] = act(X[64 x 256]) @ W^T, fp16 HMMA.
// R9 pipeline; only the activation path changed (conflict-free tables).
// ---------------------------------------------------------------------------
__global__ void __launch_bounds__(NTHR, 2)
kan_main(const float* __restrict__ x, float* __restrict__ out) {
    extern __shared__ __align__(1024) char smem[];
    const int tid = threadIdx.x;
    const int wid = tid >> 5;
    const int lid = tid & 31;
    const int m0  = blockIdx.x * BM;

    const uint32_t sbase = smem_u32(smem);

    // warp tile: 32 (M) x 64 (N); 8 warps = 2 (M) x 4 (N)
    const int wm = (wid >> 2) * 32;
    const int wn = (wid & 3) * 64;

    // ---- stage tables (stab: 8 granules, ctab: 152 granules) ----
    if (tid < 160) {
        if (tid < 8)
            ((float4*)(smem + OFF_STAB))[tid] = g_stab[tid];
        else
            ((float4*)(smem + OFF_CTAB))[tid - 8] = ((const float4*)g_ctab)[tid - 8];
    }
    // ---- issue B chunk 0 ----
    {
        uint32_t dh = sbase + OFF_B;
#pragma unroll
        for (int i = 0; i < 8; i++) {
            int idx = tid + i * NTHR;                // 0..2047 granules
            CP_ASYNC16(dh + idx * 16, (const char*)g_Bf[0] + idx * 16);
        }
        CP_COMMIT();
    }

    // ---- x chunk 0 ----
    const int arow = tid >> 2;          // 0..63
    const int aq   = tid & 3;           // k-quarter (16 elems)
    const float4* xbase = (const float4*)(x + (size_t)(m0 + arow) * KDIM + aq * 16);
    float4 xv0 = xbase[0], xv1 = xbase[1], xv2 = xbase[2], xv3 = xbase[3];

    __syncthreads();                    // tables visible
    const float4* stab = (const float4*)(smem + OFF_STAB);
    const char*   ctab = smem + OFF_CTAB;

    // activation writer constants
    const int swg0 = ((aq * 2)     ^ (arow & 7)) << 4;
    const int swg1 = ((aq * 2 + 1) ^ (arow & 7)) << 4;

    // ---- act(0) -> A buf 0 ----
    {
        float av[16] = {xv0.x, xv0.y, xv0.z, xv0.w, xv1.x, xv1.y, xv1.z, xv1.w,
                        xv2.x, xv2.y, xv2.z, xv2.w, xv3.x, xv3.y, xv3.z, xv3.w};
        float r[16];
        act16(av, aq * 16, ctab, stab, r);
        char* ad = smem + OFF_A + arow * 128;
        *(uint4*)(ad + swg0) = make_uint4(pack_h2(r[0], r[1]),  pack_h2(r[2], r[3]),
                                          pack_h2(r[4], r[5]),  pack_h2(r[6], r[7]));
        *(uint4*)(ad + swg1) = make_uint4(pack_h2(r[8], r[9]),  pack_h2(r[10], r[11]),
                                          pack_h2(r[12], r[13]), pack_h2(r[14], r[15]));
    }

    float acc[2][8][4];
#pragma unroll
    for (int mt = 0; mt < 2; mt++)
#pragma unroll
        for (int nt = 0; nt < 8; nt++)
#pragma unroll
            for (int e = 0; e < 4; e++) acc[mt][nt][e] = 0.0f;

    const int lr   = lid & 15;          // ldmatrix row within 16
    const int lhal = lid >> 4;          // k-granule half

#pragma unroll
    for (int c = 0; c < NCHUNK; c++) {
        const int s = c & 1;

        CP_WAIT0();                     // B(c) landed (only group in flight)
        __syncthreads();                // A(c)+B(c) visible; MMA(c-1) reads done

        // ---- prefetch chunk c+1: B via cp.async, x via LDG ----
        if (c < NCHUNK - 1) {
            uint32_t dh = sbase + OFF_B + (s ^ 1) * B_BUF;
#pragma unroll
            for (int i = 0; i < 8; i++) {
                int idx = tid + i * NTHR;
                CP_ASYNC16(dh + idx * 16, (const char*)g_Bf[c + 1] + idx * 16);
            }
            CP_COMMIT();
            const float4* xp = xbase + (c + 1) * (KC / 4);
            xv0 = xp[0]; xv1 = xp[1]; xv2 = xp[2]; xv3 = xp[3];
        }

        // ---- MMA(c): 4 ksteps, single fp16 pass ----
        const uint32_t aBase = sbase + OFF_A + s * A_BUF;
        const uint32_t bBase = sbase + OFF_B + s * B_BUF;
#pragma unroll
        for (int ks = 0; ks < 4; ks++) {
            const int g = ks * 2 + lhal;
            uint32_t a[2][4];
#pragma unroll
            for (int mt = 0; mt < 2; mt++) {
                int r = wm + mt * 16 + lr;
                uint32_t off = (uint32_t)(r * 128 + ((g ^ (r & 7)) << 4));
                ldsm_x4(a[mt][0], a[mt][1], a[mt][2], a[mt][3], aBase + off);
            }
#pragma unroll
            for (int np = 0; np < 4; np++) {
                int r = wn + np * 16 + lr;
                uint32_t off = (uint32_t)(r * 128 + ((g ^ (r & 7)) << 4));
                uint32_t b[4];
                ldsm_x4(b[0], b[1], b[2], b[3], bBase + off);
#pragma unroll
                for (int mt = 0; mt < 2; mt++) {
                    mma_fp16(acc[mt][2 * np + 0], a[mt], b[0], b[2]);
                    mma_fp16(acc[mt][2 * np + 1], a[mt], b[1], b[3]);
                }
            }
        }

        // ---- act(c+1) -> other A buffer (overlaps tensor-pipe drain) ----
        if (c < NCHUNK - 1) {
            float av[16] = {xv0.x, xv0.y, xv0.z, xv0.w, xv1.x, xv1.y, xv1.z, xv1.w,
                            xv2.x, xv2.y, xv2.z, xv2.w, xv3.x, xv3.y, xv3.z, xv3.w};
            float r[16];
            act16(av, (c + 1) * KC + aq * 16, ctab, stab, r);
            char* ad = smem + OFF_A + (s ^ 1) * A_BUF + arow * 128;
            *(uint4*)(ad + swg0) = make_uint4(pack_h2(r[0], r[1]),  pack_h2(r[2], r[3]),
                                              pack_h2(r[4], r[5]),  pack_h2(r[6], r[7]));
            *(uint4*)(ad + swg1) = make_uint4(pack_h2(r[8], r[9]),  pack_h2(r[10], r[11]),
                                              pack_h2(r[12], r[13]), pack_h2(r[14], r[15]));
        }
    }

    // ---- epilogue: direct fp32 stores from accumulators ----
    {
        const int rq = lid >> 2;            // 0..7
        const int cq = (lid & 3) * 2;       // 0,2,4,6
#pragma unroll
        for (int mt = 0; mt < 2; mt++) {
            int row = m0 + wm + mt * 16 + rq;
#pragma unroll
            for (int nt = 0; nt < 8; nt++) {
                int col = wn + nt * 8 + cq;
                float2 v0 = make_float2(acc[mt][nt][0], acc[mt][nt][1]);
                float2 v1 = make_float2(acc[mt][nt][2], acc[mt][nt][3]);
                *(float2*)(out + (size_t)row * NDIM + col)       = v0;
                *(float2*)(out + (size_t)(row + 8) * NDIM + col) = v1;
            }
        }
    }
}

// ---------------------------------------------------------------------------
extern "C" void kernel_launch(void* const* d_in, const int* in_sizes, int n_in,
                              void* d_out, int out_size) {
    const float* x  = (const float*)d_in[0];   // [B,S,256] fp32
    const float* ic = (const float*)d_in[1];   // [256,5]   fp32
    const float* oc = (const float*)d_in[2];   // [256,256] fp32
    float* out = (float*)d_out;

    const int M = in_sizes[0] / KDIM;          // 65536

    cudaFuncSetAttribute(kan_main, cudaFuncAttributeMaxDynamicSharedMemorySize, SMEM_TOTAL);

    kan_prologue<<<33, 256>>>(ic, oc);
    kan_main<<<M / BM, NTHR, SMEM_TOTAL>>>(x, out);
}